// round 2
// baseline (speedup 1.0000x reference)
#include <cuda_runtime.h>

#define B_    4
#define T_    32
#define C_    132
#define N_    512
#define K_    16
#define HID_  256
#define OUTG  1024      // 4*HID
#define KB0   132       // K-dim of G0 matmul
#define KB1   260       // K-dim of G1 matmul
#define HWPLD 264       // padded row length for [pos(4); h(256)]

#define LAYER_SZ (B_*T_*260*N_)           // 17039360
#define HF_OFF   LAYER_SZ
#define CF_OFF   (HF_OFF + B_*HID_*N_)    // +524288
#define GI_OFF   (CF_OFF + B_*HID_*N_)    // +524288

// -------- scratch (static device arrays; no runtime allocation) --------
__device__ float d_g0[(size_t)B_*T_*N_*OUTG];   // [bt][n][o]   268 MB
__device__ float d_g1[B_*N_*OUTG];              // [b][m][o]      8 MB
__device__ float d_hwp[B_*N_*HWPLD];            // [b][n][264]  (pos rows 0..3, h rows 4..259)
__device__ float d_c[2][B_*N_*HID_];            // double-buffered cell state [b][m][o]
__device__ float d_wt0[KB0*OUTG];               // transposed adjusted W for G0: [c][o]
__device__ float d_wt1[KB1*OUTG];               // transposed W for G1: [c][o]
__device__ int   d_gidx[B_*T_*N_*K_];

// -------- fast-but-accurate nonlinearities (err ~1e-6, fine vs 1e-3 tol) ----
__device__ __forceinline__ float sigf(float v) {
    return __fdividef(1.f, 1.f + __expf(-v));
}
__device__ __forceinline__ float tanh_(float v) {
    return 1.f - __fdividef(2.f, __expf(2.f * v) + 1.f);
}

// -------- weight repack: wt0[c][o] = W[o][c] (c<132, cols 0..3 -= W[o][132+c]);
//          wt1[c][o] = W[o][132+c] (c<260) --------
__global__ void k_prep_w(const float* __restrict__ w) {
    int tid = blockIdx.x * blockDim.x + threadIdx.x;
    if (tid >= OUTG * KB1) return;
    int o = tid / KB1, c = tid % KB1;
    d_wt1[c * OUTG + o] = w[o * 392 + 132 + c];
    if (c < KB0) {
        float v = w[o * 392 + c];
        if (c < 4) v -= w[o * 392 + 132 + c];
        d_wt0[c * OUTG + o] = v;
    }
}

// -------- init: hwp = [pos(t=0); h0=0], c0 = 0 --------
__global__ void k_init(const float* __restrict__ x) {
    int tid = blockIdx.x * blockDim.x + threadIdx.x;
    const int total1 = B_ * N_ * HWPLD;
    if (tid < total1) {
        int j = tid % HWPLD;
        int bn = tid / HWPLD;
        int b = bn / N_, n = bn % N_;
        float v = 0.f;
        if (j < 4) v = x[((size_t)(b * T_ + 0) * C_ + j) * N_ + n];
        d_hwp[tid] = v;
    } else {
        int id2 = tid - total1;
        if (id2 < B_ * N_ * HID_) d_c[0][id2] = 0.f;
    }
}

// -------- copy position channels into layer_output --------
__global__ void k_copy_pos(const float* __restrict__ x, float* __restrict__ out) {
    int tid = blockIdx.x * blockDim.x + threadIdx.x;
    if (tid >= B_ * T_ * 4 * N_) return;
    int n = tid % N_;
    int c = (tid / N_) & 3;
    int bt = tid / (4 * N_);
    out[((size_t)bt * 260 + c) * N_ + n] = x[((size_t)bt * C_ + c) * N_ + n];
}

// -------- KNN: per (b,t), top-16 smallest d2 (stable ties -> lower index) ----
// FP rounding mimics XLA-CPU: qq/rr = ((x*x + y*y) + z*z) with separate rn
// mul/add; inner = Eigen-gemm fma chain in ascending k order; d2 = (qq+rr)
// minus rn(2*inner), unfused. All via intrinsics to block nvcc contraction.
__global__ __launch_bounds__(512) void k_knn(const float* __restrict__ x,
                                             float* __restrict__ out) {
    int bt = blockIdx.x;
    int b = bt / T_, t = bt % T_;
    int tr = (t == 0) ? 0 : t - 1;
    __shared__ float rx[N_], ry[N_], rz[N_], rr[N_];
    int tid = threadIdx.x;
    {
        const float* rb = x + (size_t)(b * T_ + tr) * C_ * N_;
        float a = rb[0 * N_ + tid], e = rb[1 * N_ + tid], f = rb[2 * N_ + tid];
        rx[tid] = a; ry[tid] = e; rz[tid] = f;
        rr[tid] = __fadd_rn(__fadd_rn(__fmul_rn(a, a), __fmul_rn(e, e)),
                            __fmul_rn(f, f));
    }
    __syncthreads();
    const float* qb = x + (size_t)bt * C_ * N_;
    float qx = qb[tid], qy = qb[N_ + tid], qz = qb[2 * N_ + tid];
    float qq = __fadd_rn(__fadd_rn(__fmul_rn(qx, qx), __fmul_rn(qy, qy)),
                         __fmul_rn(qz, qz));

    float bd[K_];
    int   bi[K_];
#pragma unroll
    for (int i = 0; i < K_; i++) { bd[i] = 3.4e38f; bi[i] = 0; }

    for (int m = 0; m < N_; m++) {
        float inner = __fmul_rn(qx, rx[m]);
        inner = fmaf(qy, ry[m], inner);
        inner = fmaf(qz, rz[m], inner);
        float d2 = __fsub_rn(__fadd_rn(qq, rr[m]), __fmul_rn(2.0f, inner));
        if (d2 < bd[K_ - 1]) {
            int p = K_ - 1;
            while (p > 0 && bd[p - 1] > d2) {
                bd[p] = bd[p - 1]; bi[p] = bi[p - 1]; --p;
            }
            bd[p] = d2; bi[p] = m;
        }
    }
    int*   gi = d_gidx + ((size_t)bt * N_ + tid) * K_;
    float* go = out + GI_OFF + ((size_t)bt * N_ + tid) * K_;
#pragma unroll
    for (int i = 0; i < K_; i++) { gi[i] = bi[i]; go[i] = (float)bi[i]; }
}

// -------- tiled fp32 matmul: out[n][o] = sum_c wt[c][o] * X[c][n] (+bias) ----
// MODE 0: K=132, X = input x[bt], out = d_g0[bt], bias added. gridDim.z = 128 (bt)
// MODE 1: K=260, X = d_hwp rows  , out = d_g1[b].             gridDim.z = 4 (b)
template <int MODE>
__global__ __launch_bounds__(256) void k_mm(const float* __restrict__ x,
                                            const float* __restrict__ bias) {
    const int K  = (MODE == 0) ? KB0 : KB1;
    const int NC = (K + 7) / 8;
    const int n0 = blockIdx.x * 64, o0 = blockIdx.y * 64, bz = blockIdx.z;
    const float* wt = (MODE == 0) ? d_wt0 : d_wt1;

    __shared__ float As[2][8][64];
    __shared__ float Xs[2][8][64];

    int tid = threadIdx.x;
    int tx = tid & 15, ty = tid >> 4;

    float acc[4][4];
#pragma unroll
    for (int i = 0; i < 4; i++)
#pragma unroll
        for (int j = 0; j < 4; j++) acc[i][j] = 0.f;

    auto loadA = [&](int kc, int buf) {
#pragma unroll
        for (int r = 0; r < 2; r++) {
            int e = tid + r * 256;
            int cp = e >> 6, oo = e & 63;
            int c = kc * 8 + cp;
            As[buf][cp][oo] = (c < K) ? wt[c * OUTG + o0 + oo] : 0.f;
        }
    };
    auto loadX = [&](int kc, int buf) {
        if (MODE == 0) {
            const float* xb = x + (size_t)bz * C_ * N_;
#pragma unroll
            for (int r = 0; r < 2; r++) {
                int e = tid + r * 256;
                int cp = e >> 6, nn = e & 63;
                int c = kc * 8 + cp;
                Xs[buf][cp][nn] = (c < K) ? xb[(size_t)c * N_ + n0 + nn] : 0.f;
            }
        } else {
            int nn = tid >> 2, cs = (tid & 3) * 2;
            int c = kc * 8 + cs;
            const float* hb = d_hwp + ((size_t)bz * N_ + n0 + nn) * HWPLD;
            float2 v = make_float2(0.f, 0.f);
            if (c < K) v = *(const float2*)(hb + c);  // K even, c even -> c+1 valid
            Xs[buf][cs][nn]     = v.x;
            Xs[buf][cs + 1][nn] = v.y;
        }
    };

    loadA(0, 0); loadX(0, 0);
    __syncthreads();
    int buf = 0;
    for (int kc = 0; kc < NC; kc++) {
        if (kc + 1 < NC) { loadA(kc + 1, buf ^ 1); loadX(kc + 1, buf ^ 1); }
#pragma unroll
        for (int kk = 0; kk < 8; kk++) {
            float4 a  = *(const float4*)&As[buf][kk][ty * 4];
            float4 xv = *(const float4*)&Xs[buf][kk][tx * 4];
            float av[4] = {a.x, a.y, a.z, a.w};
            float xw[4] = {xv.x, xv.y, xv.z, xv.w};
#pragma unroll
            for (int i = 0; i < 4; i++)
#pragma unroll
                for (int j = 0; j < 4; j++)
                    acc[i][j] = fmaf(av[i], xw[j], acc[i][j]);
        }
        __syncthreads();
        buf ^= 1;
    }

    float bv[4] = {0.f, 0.f, 0.f, 0.f};
    if (MODE == 0) {
#pragma unroll
        for (int i = 0; i < 4; i++) bv[i] = bias[o0 + ty * 4 + i];
    }
    float* dst = (MODE == 0) ? (d_g0 + (size_t)bz * N_ * OUTG)
                             : (d_g1 + (size_t)bz * N_ * OUTG);
#pragma unroll
    for (int j = 0; j < 4; j++) {
        float4 v = make_float4(acc[0][j] + bv[0], acc[1][j] + bv[1],
                               acc[2][j] + bv[2], acc[3][j] + bv[3]);
        *(float4*)&dst[(size_t)(n0 + tx * 4 + j) * OUTG + o0 + ty * 4] = v;
    }
}

// -------- per-step LSTM elementwise with gather + max over k --------
__global__ __launch_bounds__(256) void k_lstm(const float* __restrict__ x,
                                              float* __restrict__ out, int t) {
    int n = blockIdx.x, b = blockIdx.y;
    int bt = b * T_ + t;
    int o = threadIdx.x;

    __shared__ int sidx[K_];
    if (o < K_) sidx[o] = d_gidx[((size_t)bt * N_ + n) * K_ + o];
    __syncthreads();

    const float* g0 = d_g0 + ((size_t)bt * N_ + n) * OUTG;
    float gi0 = g0[o], gf0 = g0[o + 256], go0 = g0[o + 512], gg0 = g0[o + 768];

    const float* cr  = d_c[t & 1] + (size_t)b * N_ * HID_;
    float*       cw  = d_c[(t & 1) ^ 1] + (size_t)b * N_ * HID_;
    const float* g1b = d_g1 + (size_t)b * N_ * OUTG;

    float hmax = -3.4e38f, cmax = -3.4e38f;
#pragma unroll 4
    for (int k = 0; k < K_; k++) {
        int m = sidx[k];
        const float* g1 = g1b + (size_t)m * OUTG;
        float gi = gi0 + g1[o];
        float gf = gf0 + g1[o + 256];
        float go = go0 + g1[o + 512];
        float gg = gg0 + g1[o + 768];
        float cp = cr[(size_t)m * HID_ + o];
        float i_ = sigf(gi), f_ = sigf(gf), oo_ = sigf(go), g_ = tanh_(gg);
        float cn = f_ * cp + i_ * g_;
        float hn = oo_ * tanh_(cn);
        hmax = fmaxf(hmax, hn);
        cmax = fmaxf(cmax, cn);
    }

    cw[(size_t)n * HID_ + o] = cmax;
    float* hw = d_hwp + ((size_t)b * N_ + n) * HWPLD;
    hw[4 + o] = hmax;
    if (o < 4) hw[o] = x[((size_t)bt * C_ + o) * N_ + n];  // pos rows for step t+1

    out[((size_t)bt * 260 + 4 + o) * N_ + n] = hmax;
    if (t == T_ - 1) {
        out[HF_OFF + ((size_t)b * HID_ + o) * N_ + n] = hmax;
        out[CF_OFF + ((size_t)b * HID_ + o) * N_ + n] = cmax;
    }
}

extern "C" void kernel_launch(void* const* d_in, const int* in_sizes, int n_in,
                              void* d_out, int out_size) {
    const float* x    = (const float*)d_in[0];
    const float* w    = (const float*)d_in[1];
    const float* bias = (const float*)d_in[2];
    float* out = (float*)d_out;

    k_prep_w<<<(OUTG * KB1 + 255) / 256, 256>>>(w);
    {
        int initN = B_ * N_ * HWPLD + B_ * N_ * HID_;
        k_init<<<(initN + 255) / 256, 256>>>(x);
    }
    k_copy_pos<<<(B_ * T_ * 4 * N_ + 255) / 256, 256>>>(x, out);
    k_knn<<<B_ * T_, 512>>>(x, out);

    // all-(b,t) G0 precompute
    k_mm<0><<<dim3(8, 16, B_ * T_), 256>>>(x, bias);

    // sequential scan
    for (int t = 0; t < T_; t++) {
        k_mm<1><<<dim3(8, 16, B_), 256>>>(x, bias);
        k_lstm<<<dim3(N_, B_), 256>>>(x, out, t);
    }
}

// round 4
// speedup vs baseline: 1.4287x; 1.4287x over previous
#include <cuda_runtime.h>

#define B_    4
#define T_    32
#define C_    132
#define N_    512
#define K_    16
#define HID_  256
#define OUTG  1024      // 4*HID
#define KB0   132       // K-dim of G0 matmul
#define KB1   260       // K-dim of G1 matmul

#define LAYER_SZ (B_*T_*260*N_)           // 17039360
#define HF_OFF   LAYER_SZ
#define CF_OFF   (HF_OFF + B_*HID_*N_)    // +524288
#define GI_OFF   (CF_OFF + B_*HID_*N_)    // +524288

// -------- scratch (static device arrays; no runtime allocation) --------
__device__ float d_g0[(size_t)B_*T_*N_*OUTG];   // [bt][n][o]   268 MB
__device__ float d_g1[B_*N_*OUTG];              // [b][m][o]      8 MB
__device__ float d_hwp[B_*KB1*N_];              // [b][c][n]  c: 0..3 pos, 4..259 h
__device__ float d_c[2][B_*N_*HID_];            // double-buffered cell state [b][m][o]
__device__ float d_wt0[KB0*OUTG];               // transposed adjusted W for G0: [c][o]
__device__ float d_wt1[KB1*OUTG];               // transposed W for G1: [c][o]
__device__ int   d_gidx[B_*T_*N_*K_];

typedef unsigned long long u64;
__device__ __forceinline__ u64 ffma2(u64 a, u64 b, u64 c) {
    u64 d;
    asm("fma.rn.f32x2 %0,%1,%2,%3;" : "=l"(d) : "l"(a), "l"(b), "l"(c));
    return d;
}
__device__ __forceinline__ u64 dup2(float x) {
    u64 r;
    asm("mov.b64 %0,{%1,%1};" : "=l"(r) : "f"(x));
    return r;
}
__device__ __forceinline__ void unpack2(u64 v, float& x, float& y) {
    asm("mov.b64 {%0,%1},%2;" : "=f"(x), "=f"(y) : "l"(v));
}

// -------- fast-but-accurate nonlinearities (err ~1e-6, fine vs 1e-3 tol) ----
__device__ __forceinline__ float sigf(float v) {
    return __fdividef(1.f, 1.f + __expf(-v));
}
__device__ __forceinline__ float tanh_(float v) {
    return 1.f - __fdividef(2.f, __expf(2.f * v) + 1.f);
}

// -------- weight repack --------
__global__ void k_prep_w(const float* __restrict__ w) {
    int tid = blockIdx.x * blockDim.x + threadIdx.x;
    if (tid >= OUTG * KB1) return;
    int o = tid / KB1, c = tid % KB1;
    d_wt1[c * OUTG + o] = w[o * 392 + 132 + c];
    if (c < KB0) {
        float v = w[o * 392 + c];
        if (c < 4) v -= w[o * 392 + 132 + c];
        d_wt0[c * OUTG + o] = v;
    }
}

// -------- init: hwp[b][c][n] = pos(t=0) for c<4 else 0 ; c0 = 0 --------
__global__ void k_init(const float* __restrict__ x) {
    int tid = blockIdx.x * blockDim.x + threadIdx.x;
    const int total1 = B_ * KB1 * N_;
    if (tid < total1) {
        int n = tid % N_;
        int c = (tid / N_) % KB1;
        int b = tid / (KB1 * N_);
        float v = 0.f;
        if (c < 4) v = x[((size_t)(b * T_ + 0) * C_ + c) * N_ + n];
        d_hwp[tid] = v;
    } else {
        int id2 = tid - total1;
        if (id2 < B_ * N_ * HID_) d_c[0][id2] = 0.f;
    }
}

// -------- copy position channels into layer_output --------
__global__ void k_copy_pos(const float* __restrict__ x, float* __restrict__ out) {
    int tid = blockIdx.x * blockDim.x + threadIdx.x;
    if (tid >= B_ * T_ * 4 * N_) return;
    int n = tid % N_;
    int c = (tid / N_) & 3;
    int bt = tid / (4 * N_);
    out[((size_t)bt * 260 + c) * N_ + n] = x[((size_t)bt * C_ + c) * N_ + n];
}

// -------- KNN: top-16 smallest d2, XLA-CPU-matching fp rounding.
// Register-resident shift-insert: the swap predicate uses the ORIGINAL d2
// (monotone over the sorted list), so all slots >= insertion point swap,
// forming a true shift chain — bit-identical to stable insertion sort,
// including equal-distance tie-breaking (lower index first). --------
__global__ __launch_bounds__(512) void k_knn(const float* __restrict__ x,
                                             float* __restrict__ out) {
    int bt = blockIdx.x;
    int b = bt / T_, t = bt % T_;
    int tr = (t == 0) ? 0 : t - 1;
    __shared__ float rx[N_], ry[N_], rz[N_], rr[N_];
    int tid = threadIdx.x;
    {
        const float* rb = x + (size_t)(b * T_ + tr) * C_ * N_;
        float a = rb[0 * N_ + tid], e = rb[1 * N_ + tid], f = rb[2 * N_ + tid];
        rx[tid] = a; ry[tid] = e; rz[tid] = f;
        rr[tid] = __fadd_rn(__fadd_rn(__fmul_rn(a, a), __fmul_rn(e, e)),
                            __fmul_rn(f, f));
    }
    __syncthreads();
    const float* qb = x + (size_t)bt * C_ * N_;
    float qx = qb[tid], qy = qb[N_ + tid], qz = qb[2 * N_ + tid];
    float qq = __fadd_rn(__fadd_rn(__fmul_rn(qx, qx), __fmul_rn(qy, qy)),
                         __fmul_rn(qz, qz));

    float bd[K_];
    int   bi[K_];
#pragma unroll
    for (int i = 0; i < K_; i++) { bd[i] = 3.4e38f; bi[i] = 0; }

    for (int m = 0; m < N_; m++) {
        float inner = __fmul_rn(qx, rx[m]);
        inner = fmaf(qy, ry[m], inner);
        inner = fmaf(qz, rz[m], inner);
        float d2 = __fsub_rn(__fadd_rn(qq, rr[m]), __fmul_rn(2.0f, inner));
        if (d2 < bd[K_ - 1]) {
            float cv = d2; int ci = m;
#pragma unroll
            for (int i = 0; i < K_; i++) {
                bool sm = d2 < bd[i];   // original d2: monotone -> shift chain
                float tf = bd[i]; int ti = bi[i];
                bd[i] = sm ? cv : bd[i];
                bi[i] = sm ? ci : bi[i];
                cv = sm ? tf : cv;
                ci = sm ? ti : ci;
            }
        }
    }
    int*   gi = d_gidx + ((size_t)bt * N_ + tid) * K_;
    float* go = out + GI_OFF + ((size_t)bt * N_ + tid) * K_;
#pragma unroll
    for (int i = 0; i < K_; i++) { gi[i] = bi[i]; go[i] = (float)bi[i]; }
}

// -------- combined tiled fp32 matmul (FFMA2): out[n][o] = wt[c][o]*X[c][n] ----
// blockIdx.z (+zoff): z<4  -> mode1: g1[b=z] = wt1 @ hwp[b]   (K=260, no bias)
//                     z>=4 -> mode0: g0[b=z-4, tt] = wt0 @ x  (K=132, +bias)
// tile: 64 n x 128 o, 256 threads, micro-tile 4n x 8o, o-paired FFMA2.
__global__ __launch_bounds__(256) void k_mm_step(const float* __restrict__ x,
                                                 const float* __restrict__ bias,
                                                 int tt, int zoff) {
    int zz = blockIdx.z + zoff;
    bool mode0 = (zz >= 4);
    if (mode0 && tt >= T_) return;
    int b = mode0 ? zz - 4 : zz;
    int n0 = blockIdx.x * 64, o0 = blockIdx.y * 128;

    int K;
    const float* src;
    const float* wt;
    float* dst;
    if (mode0) {
        K = KB0; wt = d_wt0;
        int bt = b * T_ + tt;
        src = x + (size_t)bt * C_ * N_;
        dst = d_g0 + (size_t)bt * N_ * OUTG;
    } else {
        K = KB1; wt = d_wt1;
        src = d_hwp + (size_t)b * KB1 * N_;
        dst = d_g1 + (size_t)b * N_ * OUTG;
    }
    const int NC = (K + 7) / 8;

    __shared__ float As[2][8][128];
    __shared__ float Xs[2][8][64];

    int tid = threadIdx.x;
    int tx = tid & 15;        // n: tx*4
    int ty = tid >> 4;        // o: ty*8

    u64 acc[4][4];            // [o-pair][n]
#pragma unroll
    for (int i = 0; i < 4; i++)
#pragma unroll
        for (int j = 0; j < 4; j++) acc[i][j] = 0ull;

    auto loadA = [&](int kc, int bf) {
#pragma unroll
        for (int r = 0; r < 4; r++) {
            int e = tid + r * 256;
            int cp = e >> 7, oo = e & 127;
            int c = kc * 8 + cp;
            As[bf][cp][oo] = (c < K) ? wt[c * OUTG + o0 + oo] : 0.f;
        }
    };
    auto loadX = [&](int kc, int bf) {
#pragma unroll
        for (int r = 0; r < 2; r++) {
            int e = tid + r * 256;
            int cp = e >> 6, nn = e & 63;
            int c = kc * 8 + cp;
            Xs[bf][cp][nn] = (c < K) ? src[(size_t)c * N_ + n0 + nn] : 0.f;
        }
    };

    loadA(0, 0); loadX(0, 0);
    __syncthreads();
    int buf = 0;
    for (int kc = 0; kc < NC; kc++) {
        if (kc + 1 < NC) { loadA(kc + 1, buf ^ 1); loadX(kc + 1, buf ^ 1); }
#pragma unroll
        for (int kk = 0; kk < 8; kk++) {
            ulonglong2 a01 = *(const ulonglong2*)&As[buf][kk][ty * 8];
            ulonglong2 a23 = *(const ulonglong2*)&As[buf][kk][ty * 8 + 4];
            float4 xv = *(const float4*)&Xs[buf][kk][tx * 4];
            u64 ap[4] = {a01.x, a01.y, a23.x, a23.y};
            u64 xd[4] = {dup2(xv.x), dup2(xv.y), dup2(xv.z), dup2(xv.w)};
#pragma unroll
            for (int i = 0; i < 4; i++)
#pragma unroll
                for (int j = 0; j < 4; j++)
                    acc[i][j] = ffma2(ap[i], xd[j], acc[i][j]);
        }
        __syncthreads();
        buf ^= 1;
    }

    float bv[8];
#pragma unroll
    for (int i = 0; i < 8; i++) bv[i] = 0.f;
    if (mode0) {
#pragma unroll
        for (int i = 0; i < 8; i++) bv[i] = bias[o0 + ty * 8 + i];
    }
#pragma unroll
    for (int j = 0; j < 4; j++) {
        float f[8];
#pragma unroll
        for (int i = 0; i < 4; i++) unpack2(acc[i][j], f[2 * i], f[2 * i + 1]);
#pragma unroll
        for (int i = 0; i < 8; i++) f[i] += bv[i];
        float* dp = &dst[(size_t)(n0 + tx * 4 + j) * OUTG + o0 + ty * 8];
        *(float4*)dp       = make_float4(f[0], f[1], f[2], f[3]);
        *(float4*)(dp + 4) = make_float4(f[4], f[5], f[6], f[7]);
    }
}

// -------- per-step LSTM elementwise with gather + max over k --------
__global__ __launch_bounds__(256) void k_lstm(const float* __restrict__ x,
                                              float* __restrict__ out, int t) {
    int n = blockIdx.x, b = blockIdx.y;
    int bt = b * T_ + t;
    int o = threadIdx.x;

    __shared__ int sidx[K_];
    if (o < K_) sidx[o] = d_gidx[((size_t)bt * N_ + n) * K_ + o];
    __syncthreads();

    const float* g0 = d_g0 + ((size_t)bt * N_ + n) * OUTG;
    float gi0 = g0[o], gf0 = g0[o + 256], go0 = g0[o + 512], gg0 = g0[o + 768];

    const float* cr  = d_c[t & 1] + (size_t)b * N_ * HID_;
    float*       cw  = d_c[(t & 1) ^ 1] + (size_t)b * N_ * HID_;
    const float* g1b = d_g1 + (size_t)b * N_ * OUTG;

    float hmax = -3.4e38f, cmax = -3.4e38f;
#pragma unroll 4
    for (int k = 0; k < K_; k++) {
        int m = sidx[k];
        const float* g1 = g1b + (size_t)m * OUTG;
        float gi = gi0 + g1[o];
        float gf = gf0 + g1[o + 256];
        float go = go0 + g1[o + 512];
        float gg = gg0 + g1[o + 768];
        float cp = cr[(size_t)m * HID_ + o];
        float i_ = sigf(gi), f_ = sigf(gf), oo_ = sigf(go), g_ = tanh_(gg);
        float cn = f_ * cp + i_ * g_;
        float hn = oo_ * tanh_(cn);
        hmax = fmaxf(hmax, hn);
        cmax = fmaxf(cmax, cn);
    }

    cw[(size_t)n * HID_ + o] = cmax;

    float* hwB = d_hwp + (size_t)b * KB1 * N_;
    hwB[(size_t)(4 + o) * N_ + n] = hmax;
    if (o < 4) hwB[(size_t)o * N_ + n] = x[((size_t)bt * C_ + o) * N_ + n];

    out[((size_t)bt * 260 + 4 + o) * N_ + n] = hmax;
    if (t == T_ - 1) {
        out[HF_OFF + ((size_t)b * HID_ + o) * N_ + n] = hmax;
        out[CF_OFF + ((size_t)b * HID_ + o) * N_ + n] = cmax;
    }
}

extern "C" void kernel_launch(void* const* d_in, const int* in_sizes, int n_in,
                              void* d_out, int out_size) {
    const float* x    = (const float*)d_in[0];
    const float* w    = (const float*)d_in[1];
    const float* bias = (const float*)d_in[2];
    float* out = (float*)d_out;

    k_prep_w<<<(OUTG * KB1 + 255) / 256, 256>>>(w);
    {
        int initN = B_ * KB1 * N_ + B_ * N_ * HID_;
        k_init<<<(initN + 255) / 256, 256>>>(x);
    }
    k_copy_pos<<<(B_ * T_ * 4 * N_ + 255) / 256, 256>>>(x, out);
    k_knn<<<B_ * T_, 512>>>(x, out);

    // g0 for t=0 only (mode0 slice)
    k_mm_step<<<dim3(8, 8, 4), 256>>>(x, bias, 0, 4);

    // sequential scan; each step also computes g0 for t+1 in the same launch
    for (int t = 0; t < T_; t++) {
        k_mm_step<<<dim3(8, 8, 8), 256>>>(x, bias, t + 1, 0);
        k_lstm<<<dim3(N_, B_), 256>>>(x, out, t);
    }
}